// round 3
// baseline (speedup 1.0000x reference)
#include <cuda_runtime.h>
#include <math.h>

#define BB   128
#define TT   2048
#define INN  32
#define SS   32
#define MMH  8
#define EE   64
#define HH   128
#define G3   384   // 3*H

// Scratch (allocation-free rule: __device__ globals)
__device__ float g_gx [(size_t)BB * TT * G3];        // enc @ W_x[:64] + b_x   (384 MB)
__device__ float g_xin[(size_t)BB * TT * MMH * SS];  // x @ W_in + b_s         (256 MB)

__device__ __forceinline__ float sigmoidf_(float x) { return 1.0f / (1.0f + expf(-x)); }

// ---------------------------------------------------------------------------
// Precompute kernel: per batch b, for all t:
//   enc(t)   = tanh(x_t @ W_enc + b_enc)                (64)
//   gx(t)    = enc(t) @ W_x[0:64,:] + b_x               (384)  -> g_gx
//   xin(t)   = x_t @ W_in + b_s                         (8*32) -> g_xin
// Software-pipelined: iter t computes enc(t) & xin(t) while gx(t-1) is emitted.
// ---------------------------------------------------------------------------
__global__ void __launch_bounds__(512, 1) pre_kernel(
    const float* __restrict__ x,
    const float* __restrict__ W_enc, const float* __restrict__ b_enc,
    const float* __restrict__ W_in,  const float* __restrict__ b_s,
    const float* __restrict__ W_x,   const float* __restrict__ b_x)
{
    const int b   = blockIdx.x;
    const int tid = threadIdx.x;

    __shared__ __align__(16) float sX[2][INN];
    __shared__ __align__(16) float sEnc[2][EE];
    __shared__ __align__(16) float sWenc[INN * EE];

    for (int i = tid; i < INN * EE; i += 512) sWenc[i] = W_enc[i];

    float wx[64];  float bx = 0.f;
    float wi0[32], wi1[32]; float bs0 = 0.f, bs1 = 0.f;
    float be = 0.f;
    int e0 = 0, m = 0, d0 = 0;

    if (tid < 384) {
        bx = b_x[tid];
        #pragma unroll
        for (int i = 0; i < 64; i++) wx[i] = W_x[i * G3 + tid];
    } else {
        int q = tid - 384;
        e0 = 2 * q; m = e0 >> 5; d0 = e0 & 31;
        bs0 = b_s[m * SS + d0];
        bs1 = b_s[m * SS + d0 + 1];
        #pragma unroll
        for (int i = 0; i < 32; i++) {
            float2 w2 = *(const float2*)&W_in[m * INN * SS + i * SS + d0];
            wi0[i] = w2.x; wi1[i] = w2.y;
        }
        if (tid < 448) be = b_enc[tid - 384];
    }

    if (tid < 32) sX[0][tid] = x[((size_t)b * TT + 0) * INN + tid];
    __syncthreads();

    for (int t = 0; t <= TT; t++) {
        const int cur = t & 1, nxt = cur ^ 1;
        if (tid < 384) {
            if (t >= 1) {  // emit gx(t-1) from enc(t-1) = sEnc[nxt]
                float a = bx;
                #pragma unroll
                for (int i = 0; i < 64; i += 4) {
                    float4 ev = *(const float4*)&sEnc[nxt][i];
                    a += wx[i]*ev.x + wx[i+1]*ev.y + wx[i+2]*ev.z + wx[i+3]*ev.w;
                }
                g_gx[((size_t)b * TT + (t - 1)) * G3 + tid] = a;
            }
            if (tid < 32 && t + 1 < TT)
                sX[nxt][tid] = x[((size_t)b * TT + t + 1) * INN + tid];
        } else if (t < TT) {
            // xin(t)
            float a0 = bs0, a1 = bs1;
            #pragma unroll
            for (int i = 0; i < 32; i += 4) {
                float4 xv = *(const float4*)&sX[cur][i];
                a0 += wi0[i]*xv.x + wi0[i+1]*xv.y + wi0[i+2]*xv.z + wi0[i+3]*xv.w;
                a1 += wi1[i]*xv.x + wi1[i+1]*xv.y + wi1[i+2]*xv.z + wi1[i+3]*xv.w;
            }
            *(float2*)&g_xin[((size_t)b * TT + t) * (MMH * SS) + e0] = make_float2(a0, a1);
            // enc(t)
            if (tid < 448) {
                int c = tid - 384;
                float a = be;
                #pragma unroll
                for (int s = 0; s < 32; s++) a += sWenc[s * EE + c] * sX[cur][s];
                sEnc[cur][c] = tanhf(a);
            }
        }
        __syncthreads();
    }
}

// ---------------------------------------------------------------------------
// Sequential kernel: 1 block per batch element, 512 threads.
//   threads 0..383 : gh_j = h @ W_h[:,j] + b_h   (W_h rows 0..63 in SMEM,
//                    rows 64..127 in per-thread registers), plus gx assembly
//   threads 384..511: new_state (8x32), W_rec in registers (2 cols/thread)
//   threads 0..127 : GRU elementwise + gate-logit partials
//   warp 0         : softmax(8) + kstate update + err feedback + output
// ---------------------------------------------------------------------------
__global__ void __launch_bounds__(512, 1) seq_kernel(
    const float* __restrict__ y,
    const float* __restrict__ W_rec,
    const float* __restrict__ W_h,   const float* __restrict__ b_h,
    const float* __restrict__ W_x,
    const float* __restrict__ W_gate, const float* __restrict__ b_gate,
    float* __restrict__ out)
{
    const int b   = blockIdx.x;
    const int tid = threadIdx.x;

    extern __shared__ __align__(16) float smem[];
    float* sWh    = smem;                 // 64*384
    float* sWxl   = sWh    + 64 * G3;     // 384  (W_x row 64 = err row)
    float* sBh    = sWxl   + G3;          // 384
    float* sWgate = sBh    + G3;          // 128*8
    float* sBgate = sWgate + HH * MMH;    // 8
    float* sH     = sBgate + 8;           // 128
    float* sPre   = sH     + HH;          // 384
    float* sHn    = sPre   + G3;          // 128
    float* sNs    = sHn    + HH;          // 256
    float* sKs    = sNs    + MMH * SS;    // 32
    float* sLp    = sKs    + SS;          // 32 (4 warps x 8 logit partials)
    float* sMisc  = sLp    + 32;          // [0]=err, [1]=y_t

    for (int i = tid; i < 64 * G3; i += 512) sWh[i] = W_h[i];
    for (int i = tid; i < G3; i += 512) { sWxl[i] = W_x[64 * G3 + i]; sBh[i] = b_h[i]; }
    for (int i = tid; i < HH * MMH; i += 512) sWgate[i] = W_gate[i];
    if (tid < 8)   sBgate[tid] = b_gate[tid];
    if (tid < HH)  sH[tid]  = 0.f;
    if (tid < SS)  sKs[tid] = 0.f;
    if (tid == 0)  sMisc[0] = 0.f;

    float whreg[64];
    float wr0[32], wr1[32];
    int e0 = 0, m = 0, d0 = 0;
    if (tid < 384) {
        #pragma unroll
        for (int r = 0; r < 64; r++) whreg[r] = W_h[(64 + r) * G3 + tid];
    } else {
        int q = tid - 384;
        e0 = 2 * q; m = e0 >> 5; d0 = e0 & 31;
        #pragma unroll
        for (int s = 0; s < 32; s++) {
            float2 w2 = *(const float2*)&W_rec[m * SS * SS + s * SS + d0];
            wr0[s] = w2.x; wr1[s] = w2.y;
        }
    }
    __syncthreads();

    const float* gx_t  = g_gx  + (size_t)b * TT * G3;
    const float* xin_t = g_xin + (size_t)b * TT * (MMH * SS);
    const float* y_b   = y   + (size_t)b * TT;
    float*       out_b = out + (size_t)b * TT;

    for (int t = 0; t < TT; t++) {
        // ------------------ Phase A ------------------
        if (tid < 384) {
            float gxp = __ldg(&gx_t[tid]);   // issued early, consumed after dot
            float wxl = sWxl[tid];
            float err = sMisc[0];
            float acc = sBh[tid];
            #pragma unroll
            for (int k = 0; k < 64; k += 4) {
                float4 hv = *(const float4*)&sH[k];
                acc += sWh[(k+0)*G3 + tid]*hv.x + sWh[(k+1)*G3 + tid]*hv.y
                     + sWh[(k+2)*G3 + tid]*hv.z + sWh[(k+3)*G3 + tid]*hv.w;
            }
            #pragma unroll
            for (int r = 0; r < 64; r += 4) {
                float4 hv = *(const float4*)&sH[64 + r];
                acc += whreg[r]*hv.x + whreg[r+1]*hv.y + whreg[r+2]*hv.z + whreg[r+3]*hv.w;
            }
            float gx = gxp + err * wxl;      // full x-path pre-activation
            if (tid < 256) sPre[tid] = gx + acc;          // xz+hz, xr+hr
            else { sPre[tid] = gx; sHn[tid - 256] = acc; } // xn | hn kept apart
        } else {
            float2 xi = *(const float2*)&xin_t[e0];
            float a0 = xi.x, a1 = xi.y;
            #pragma unroll
            for (int s = 0; s < 32; s += 4) {
                float4 kv = *(const float4*)&sKs[s];
                a0 += wr0[s]*kv.x + wr0[s+1]*kv.y + wr0[s+2]*kv.z + wr0[s+3]*kv.w;
                a1 += wr1[s]*kv.x + wr1[s+1]*kv.y + wr1[s+2]*kv.z + wr1[s+3]*kv.w;
            }
            sNs[e0]     = tanhf(a0);
            sNs[e0 + 1] = tanhf(a1);
            if (tid == 511) sMisc[1] = y_b[t];
        }
        __syncthreads();  // B1

        // ------------------ Phase B: GRU + logit partials ------------------
        if (tid < HH) {
            float z  = sigmoidf_(sPre[tid]);
            float r  = sigmoidf_(sPre[HH + tid]);
            float n  = tanhf(sPre[2 * HH + tid] + r * sHn[tid]);
            float hn = (1.f - z) * n + z * sH[tid];
            sH[tid] = hn;
            float4 wg0 = *(const float4*)&sWgate[tid * 8];
            float4 wg1 = *(const float4*)&sWgate[tid * 8 + 4];
            float p[8];
            p[0]=hn*wg0.x; p[1]=hn*wg0.y; p[2]=hn*wg0.z; p[3]=hn*wg0.w;
            p[4]=hn*wg1.x; p[5]=hn*wg1.y; p[6]=hn*wg1.z; p[7]=hn*wg1.w;
            #pragma unroll
            for (int off = 16; off > 0; off >>= 1) {
                #pragma unroll
                for (int j = 0; j < 8; j++)
                    p[j] += __shfl_down_sync(0xffffffffu, p[j], off);
            }
            if ((tid & 31) == 0) {
                int w = tid >> 5;
                #pragma unroll
                for (int j = 0; j < 8; j++) sLp[w * 8 + j] = p[j];
            }
        }
        __syncthreads();  // B2

        // ------------------ Phase C: softmax gate + kstate + err ------------------
        if (tid < 32) {
            float g = 0.f;
            if (tid < 8) {
                float lg = sLp[tid] + sLp[8 + tid] + sLp[16 + tid] + sLp[24 + tid]
                         + sBgate[tid];
                float mx = lg;
                #pragma unroll
                for (int off = 4; off > 0; off >>= 1)
                    mx = fmaxf(mx, __shfl_xor_sync(0x000000ffu, mx, off));
                float ex = expf(lg - mx);
                float sm = ex;
                #pragma unroll
                for (int off = 4; off > 0; off >>= 1)
                    sm += __shfl_xor_sync(0x000000ffu, sm, off);
                g = ex / sm;
            }
            float ks = 0.f;
            #pragma unroll
            for (int mm = 0; mm < 8; mm++) {
                float gm = __shfl_sync(0xffffffffu, g, mm);
                ks += gm * sNs[mm * SS + tid];
            }
            sKs[tid] = ks;
            if (tid == 31) {
                sMisc[0] = ks - sMisc[1];   // err = pred - y_t
                out_b[t] = ks;              // pred = kstate_new[S-1]
            }
        }
        __syncthreads();  // B3

        gx_t  += G3;
        xin_t += MMH * SS;
    }
}

// ---------------------------------------------------------------------------
extern "C" void kernel_launch(void* const* d_in, const int* in_sizes, int n_in,
                              void* d_out, int out_size)
{
    const float* x      = (const float*)d_in[0];
    const float* y      = (const float*)d_in[1];
    const float* W_enc  = (const float*)d_in[2];
    const float* b_enc  = (const float*)d_in[3];
    const float* W_in   = (const float*)d_in[4];
    const float* W_rec  = (const float*)d_in[5];
    const float* b_s    = (const float*)d_in[6];
    const float* W_x    = (const float*)d_in[7];
    const float* W_h    = (const float*)d_in[8];
    const float* b_x    = (const float*)d_in[9];
    const float* b_h    = (const float*)d_in[10];
    const float* W_gate = (const float*)d_in[11];
    const float* b_gate = (const float*)d_in[12];
    float* out = (float*)d_out;

    const int SMEM_SEQ = (64*G3 + G3 + G3 + HH*MMH + 8 + HH + G3 + HH
                          + MMH*SS + SS + 32 + 4) * (int)sizeof(float);

    cudaFuncSetAttribute(seq_kernel, cudaFuncAttributeMaxDynamicSharedMemorySize, SMEM_SEQ);

    pre_kernel<<<BB, 512>>>(x, W_enc, b_enc, W_in, b_s, W_x, b_x);
    seq_kernel<<<BB, 512, SMEM_SEQ>>>(y, W_rec, W_h, b_h, W_x, W_gate, b_gate, out);
}

// round 4
// speedup vs baseline: 1.0069x; 1.0069x over previous
#include <cuda_runtime.h>
#include <math.h>

#define BB   128
#define TT   2048
#define INN  32
#define SS   32
#define MMH  8
#define EE   64
#define HH   128
#define G3   384   // 3*H

// Scratch (allocation-free rule: __device__ globals)
__device__ float g_gx [(size_t)BB * TT * G3];        // enc @ W_x[:64] + b_x   (384 MB)
__device__ float g_xin[(size_t)BB * TT * MMH * SS];  // x @ W_in + b_s         (256 MB)

__device__ __forceinline__ float sigmoidf_(float x) { return 1.0f / (1.0f + expf(-x)); }

// ---------------------------------------------------------------------------
// Precompute kernel: per batch b, for all t:
//   enc(t)   = tanh(x_t @ W_enc + b_enc)                (64)
//   gx(t)    = enc(t) @ W_x[0:64,:] + b_x               (384)  -> g_gx
//   xin(t)   = x_t @ W_in + b_s                         (8*32) -> g_xin
// Software-pipelined: iter t computes enc(t) & xin(t) while gx(t-1) is emitted.
// ---------------------------------------------------------------------------
__global__ void __launch_bounds__(512, 1) pre_kernel(
    const float* __restrict__ x,
    const float* __restrict__ W_enc, const float* __restrict__ b_enc,
    const float* __restrict__ W_in,  const float* __restrict__ b_s,
    const float* __restrict__ W_x,   const float* __restrict__ b_x)
{
    const int b   = blockIdx.x;
    const int tid = threadIdx.x;

    __shared__ __align__(16) float sX[2][INN];
    __shared__ __align__(16) float sEnc[2][EE];
    __shared__ __align__(16) float sWenc[INN * EE];

    for (int i = tid; i < INN * EE; i += 512) sWenc[i] = W_enc[i];

    float wx[64];  float bx = 0.f;
    float wi0[32], wi1[32]; float bs0 = 0.f, bs1 = 0.f;
    float be = 0.f;
    int e0 = 0, m = 0, d0 = 0;

    if (tid < 384) {
        bx = b_x[tid];
        #pragma unroll
        for (int i = 0; i < 64; i++) wx[i] = W_x[i * G3 + tid];
    } else {
        int q = tid - 384;
        e0 = 2 * q; m = e0 >> 5; d0 = e0 & 31;
        bs0 = b_s[m * SS + d0];
        bs1 = b_s[m * SS + d0 + 1];
        #pragma unroll
        for (int i = 0; i < 32; i++) {
            float2 w2 = *(const float2*)&W_in[m * INN * SS + i * SS + d0];
            wi0[i] = w2.x; wi1[i] = w2.y;
        }
        if (tid < 448) be = b_enc[tid - 384];
    }

    if (tid < 32) sX[0][tid] = x[((size_t)b * TT + 0) * INN + tid];
    __syncthreads();

    for (int t = 0; t <= TT; t++) {
        const int cur = t & 1, nxt = cur ^ 1;
        if (tid < 384) {
            if (t >= 1) {  // emit gx(t-1) from enc(t-1) = sEnc[nxt]
                float a = bx;
                #pragma unroll
                for (int i = 0; i < 64; i += 4) {
                    float4 ev = *(const float4*)&sEnc[nxt][i];
                    a += wx[i]*ev.x + wx[i+1]*ev.y + wx[i+2]*ev.z + wx[i+3]*ev.w;
                }
                g_gx[((size_t)b * TT + (t - 1)) * G3 + tid] = a;
            }
            if (tid < 32 && t + 1 < TT)
                sX[nxt][tid] = x[((size_t)b * TT + t + 1) * INN + tid];
        } else if (t < TT) {
            // xin(t)
            float a0 = bs0, a1 = bs1;
            #pragma unroll
            for (int i = 0; i < 32; i += 4) {
                float4 xv = *(const float4*)&sX[cur][i];
                a0 += wi0[i]*xv.x + wi0[i+1]*xv.y + wi0[i+2]*xv.z + wi0[i+3]*xv.w;
                a1 += wi1[i]*xv.x + wi1[i+1]*xv.y + wi1[i+2]*xv.z + wi1[i+3]*xv.w;
            }
            *(float2*)&g_xin[((size_t)b * TT + t) * (MMH * SS) + e0] = make_float2(a0, a1);
            // enc(t)
            if (tid < 448) {
                int c = tid - 384;
                float a = be;
                #pragma unroll
                for (int s = 0; s < 32; s++) a += sWenc[s * EE + c] * sX[cur][s];
                sEnc[cur][c] = tanhf(a);
            }
        }
        __syncthreads();
    }
}

// ---------------------------------------------------------------------------
// Sequential kernel: 1 block per batch element, 512 threads.
//   threads 0..383 : gh_j = h @ W_h[:,j] + b_h   (W_h rows 0..63 in SMEM,
//                    rows 64..127 in per-thread registers), plus gx assembly
//   threads 384..511: new_state (8x32), W_rec in registers (2 cols/thread)
//   threads 0..127 : GRU elementwise + gate-logit partials
//   warp 0         : softmax(8) + kstate update + err feedback + output
// ---------------------------------------------------------------------------
__global__ void __launch_bounds__(512, 1) seq_kernel(
    const float* __restrict__ y,
    const float* __restrict__ W_rec,
    const float* __restrict__ W_h,   const float* __restrict__ b_h,
    const float* __restrict__ W_x,
    const float* __restrict__ W_gate, const float* __restrict__ b_gate,
    float* __restrict__ out)
{
    const int b   = blockIdx.x;
    const int tid = threadIdx.x;

    extern __shared__ __align__(16) float smem[];
    float* sWh    = smem;                 // 64*384
    float* sWxl   = sWh    + 64 * G3;     // 384  (W_x row 64 = err row)
    float* sBh    = sWxl   + G3;          // 384
    float* sWgate = sBh    + G3;          // 128*8
    float* sBgate = sWgate + HH * MMH;    // 8
    float* sH     = sBgate + 8;           // 128
    float* sPre   = sH     + HH;          // 384
    float* sHn    = sPre   + G3;          // 128
    float* sNs    = sHn    + HH;          // 256
    float* sKs    = sNs    + MMH * SS;    // 32
    float* sLp    = sKs    + SS;          // 32 (4 warps x 8 logit partials)
    float* sMisc  = sLp    + 32;          // [0]=err, [1]=y_t

    for (int i = tid; i < 64 * G3; i += 512) sWh[i] = W_h[i];
    for (int i = tid; i < G3; i += 512) { sWxl[i] = W_x[64 * G3 + i]; sBh[i] = b_h[i]; }
    for (int i = tid; i < HH * MMH; i += 512) sWgate[i] = W_gate[i];
    if (tid < 8)   sBgate[tid] = b_gate[tid];
    if (tid < HH)  sH[tid]  = 0.f;
    if (tid < SS)  sKs[tid] = 0.f;
    if (tid == 0)  sMisc[0] = 0.f;

    float whreg[64];
    float wr0[32], wr1[32];
    int e0 = 0, m = 0, d0 = 0;
    if (tid < 384) {
        #pragma unroll
        for (int r = 0; r < 64; r++) whreg[r] = W_h[(64 + r) * G3 + tid];
    } else {
        int q = tid - 384;
        e0 = 2 * q; m = e0 >> 5; d0 = e0 & 31;
        #pragma unroll
        for (int s = 0; s < 32; s++) {
            float2 w2 = *(const float2*)&W_rec[m * SS * SS + s * SS + d0];
            wr0[s] = w2.x; wr1[s] = w2.y;
        }
    }
    __syncthreads();

    const float* gx_t  = g_gx  + (size_t)b * TT * G3;
    const float* xin_t = g_xin + (size_t)b * TT * (MMH * SS);
    const float* y_b   = y   + (size_t)b * TT;
    float*       out_b = out + (size_t)b * TT;

    for (int t = 0; t < TT; t++) {
        // ------------------ Phase A ------------------
        if (tid < 384) {
            float gxp = __ldg(&gx_t[tid]);   // issued early, consumed after dot
            float wxl = sWxl[tid];
            float err = sMisc[0];
            float acc = sBh[tid];
            #pragma unroll
            for (int k = 0; k < 64; k += 4) {
                float4 hv = *(const float4*)&sH[k];
                acc += sWh[(k+0)*G3 + tid]*hv.x + sWh[(k+1)*G3 + tid]*hv.y
                     + sWh[(k+2)*G3 + tid]*hv.z + sWh[(k+3)*G3 + tid]*hv.w;
            }
            #pragma unroll
            for (int r = 0; r < 64; r += 4) {
                float4 hv = *(const float4*)&sH[64 + r];
                acc += whreg[r]*hv.x + whreg[r+1]*hv.y + whreg[r+2]*hv.z + whreg[r+3]*hv.w;
            }
            float gx = gxp + err * wxl;      // full x-path pre-activation
            if (tid < 256) sPre[tid] = gx + acc;          // xz+hz, xr+hr
            else { sPre[tid] = gx; sHn[tid - 256] = acc; } // xn | hn kept apart
        } else {
            float2 xi = *(const float2*)&xin_t[e0];
            float a0 = xi.x, a1 = xi.y;
            #pragma unroll
            for (int s = 0; s < 32; s += 4) {
                float4 kv = *(const float4*)&sKs[s];
                a0 += wr0[s]*kv.x + wr0[s+1]*kv.y + wr0[s+2]*kv.z + wr0[s+3]*kv.w;
                a1 += wr1[s]*kv.x + wr1[s+1]*kv.y + wr1[s+2]*kv.z + wr1[s+3]*kv.w;
            }
            sNs[e0]     = tanhf(a0);
            sNs[e0 + 1] = tanhf(a1);
            if (tid == 511) sMisc[1] = y_b[t];
        }
        __syncthreads();  // B1

        // ------------------ Phase B: GRU + logit partials ------------------
        if (tid < HH) {
            float z  = sigmoidf_(sPre[tid]);
            float r  = sigmoidf_(sPre[HH + tid]);
            float n  = tanhf(sPre[2 * HH + tid] + r * sHn[tid]);
            float hn = (1.f - z) * n + z * sH[tid];
            sH[tid] = hn;
            float4 wg0 = *(const float4*)&sWgate[tid * 8];
            float4 wg1 = *(const float4*)&sWgate[tid * 8 + 4];
            float p[8];
            p[0]=hn*wg0.x; p[1]=hn*wg0.y; p[2]=hn*wg0.z; p[3]=hn*wg0.w;
            p[4]=hn*wg1.x; p[5]=hn*wg1.y; p[6]=hn*wg1.z; p[7]=hn*wg1.w;
            #pragma unroll
            for (int off = 16; off > 0; off >>= 1) {
                #pragma unroll
                for (int j = 0; j < 8; j++)
                    p[j] += __shfl_down_sync(0xffffffffu, p[j], off);
            }
            if ((tid & 31) == 0) {
                int w = tid >> 5;
                #pragma unroll
                for (int j = 0; j < 8; j++) sLp[w * 8 + j] = p[j];
            }
        }
        __syncthreads();  // B2

        // ------------------ Phase C: softmax gate + kstate + err ------------------
        if (tid < 32) {
            float g = 0.f;
            if (tid < 8) {
                float lg = sLp[tid] + sLp[8 + tid] + sLp[16 + tid] + sLp[24 + tid]
                         + sBgate[tid];
                float mx = lg;
                #pragma unroll
                for (int off = 4; off > 0; off >>= 1)
                    mx = fmaxf(mx, __shfl_xor_sync(0x000000ffu, mx, off));
                float ex = expf(lg - mx);
                float sm = ex;
                #pragma unroll
                for (int off = 4; off > 0; off >>= 1)
                    sm += __shfl_xor_sync(0x000000ffu, sm, off);
                g = ex / sm;
            }
            float ks = 0.f;
            #pragma unroll
            for (int mm = 0; mm < 8; mm++) {
                float gm = __shfl_sync(0xffffffffu, g, mm);
                ks += gm * sNs[mm * SS + tid];
            }
            sKs[tid] = ks;
            if (tid == 31) {
                sMisc[0] = ks - sMisc[1];   // err = pred - y_t
                out_b[t] = ks;              // pred = kstate_new[S-1]
            }
        }
        __syncthreads();  // B3

        gx_t  += G3;
        xin_t += MMH * SS;
    }
}

// ---------------------------------------------------------------------------
extern "C" void kernel_launch(void* const* d_in, const int* in_sizes, int n_in,
                              void* d_out, int out_size)
{
    const float* x      = (const float*)d_in[0];
    const float* y      = (const float*)d_in[1];
    const float* W_enc  = (const float*)d_in[2];
    const float* b_enc  = (const float*)d_in[3];
    const float* W_in   = (const float*)d_in[4];
    const float* W_rec  = (const float*)d_in[5];
    const float* b_s    = (const float*)d_in[6];
    const float* W_x    = (const float*)d_in[7];
    const float* W_h    = (const float*)d_in[8];
    const float* b_x    = (const float*)d_in[9];
    const float* b_h    = (const float*)d_in[10];
    const float* W_gate = (const float*)d_in[11];
    const float* b_gate = (const float*)d_in[12];
    float* out = (float*)d_out;

    const int SMEM_SEQ = (64*G3 + G3 + G3 + HH*MMH + 8 + HH + G3 + HH
                          + MMH*SS + SS + 32 + 4) * (int)sizeof(float);

    cudaFuncSetAttribute(seq_kernel, cudaFuncAttributeMaxDynamicSharedMemorySize, SMEM_SEQ);

    pre_kernel<<<BB, 512>>>(x, W_enc, b_enc, W_in, b_s, W_x, b_x);
    seq_kernel<<<BB, 512, SMEM_SEQ>>>(y, W_rec, W_h, b_h, W_x, W_gate, b_gate, out);
}